// round 5
// baseline (speedup 1.0000x reference)
#include <cuda_runtime.h>
#include <cuda_bf16.h>
#include <math.h>
#include <stdint.h>

#define T_STEPS 512
#define BATCH   64
#define IN_DIM  1024
#define HID     1024
#define GATES   4096   // 4*HID, gate order i,g,f,o

// ---------------- device scratch ----------------
__device__ float g_wx[(size_t)T_STEPS * BATCH * GATES];   // 512 MB
__device__ float g_c[BATCH * HID];

__device__ __nv_bfloat16 g_xhi[(size_t)T_STEPS * BATCH * IN_DIM];
__device__ __nv_bfloat16 g_xlo[(size_t)T_STEPS * BATCH * IN_DIM];
__device__ __nv_bfloat16 g_Wthi[(size_t)GATES * IN_DIM];   // transposed [N][K]
__device__ __nv_bfloat16 g_Wtlo[(size_t)GATES * IN_DIM];
__device__ __nv_bfloat16 g_Rthi[(size_t)GATES * HID];      // transposed [N][K]
__device__ __nv_bfloat16 g_Rtlo[(size_t)GATES * HID];
__device__ __nv_bfloat16 g_hhi[2][BATCH * HID];            // ping-pong h in bf16 hi/lo
__device__ __nv_bfloat16 g_hlo[2][BATCH * HID];

// ---------------- mma.m16n8k16 bf16 helper ----------------
// Fragment layout (g = lane>>2, t = lane&3):
//  A row-major 16x16: a0=A[g][2t..], a1=A[g+8][2t..], a2=A[g][2t+8..], a3=A[g+8][2t+8..]
//  B col-major 16x8 stored here as Bt[n][k]: b0=Bt[g][2t..], b1=Bt[g][2t+8..]
//  C 16x8 f32: c0=C[g][2t], c1=C[g][2t+1], c2=C[g+8][2t], c3=C[g+8][2t+1]
__device__ __forceinline__ void mma16816(float* c, const uint32_t* a, const uint32_t* b)
{
    asm volatile(
        "mma.sync.aligned.m16n8k16.row.col.f32.bf16.bf16.f32 "
        "{%0,%1,%2,%3}, {%4,%5,%6,%7}, {%8,%9}, {%0,%1,%2,%3};"
        : "+f"(c[0]), "+f"(c[1]), "+f"(c[2]), "+f"(c[3])
        : "r"(a[0]), "r"(a[1]), "r"(a[2]), "r"(a[3]), "r"(b[0]), "r"(b[1]));
}

__device__ __forceinline__ void split_bf16(float v, __nv_bfloat16& hi, __nv_bfloat16& lo)
{
    hi = __float2bfloat16_rn(v);
    lo = __float2bfloat16_rn(v - __bfloat162float(hi));
}

// ---------------- conversion kernels ----------------
// All write targets are referenced directly from DEVICE code (never passed as
// kernel args from host — __device__ symbols are invalid host-side).
__global__ void convert_x(const float* __restrict__ x)
{
    size_t i = (size_t)blockIdx.x * blockDim.x + threadIdx.x;
    if (i < (size_t)T_STEPS * BATCH * IN_DIM) {
        __nv_bfloat16 hi, lo;
        split_bf16(x[i], hi, lo);
        g_xhi[i] = hi;
        g_xlo[i] = lo;
    }
}

// src [K=1024][N=4096] row-major -> g_Wt{hi,lo} [N][K] bf16 (transposed)
__global__ void convert_W(const float* __restrict__ src)
{
    __shared__ float tile[32][33];
    int n0 = blockIdx.x * 32, k0 = blockIdx.y * 32;
    int tx = threadIdx.x, ty = threadIdx.y;   // 32 x 8
#pragma unroll
    for (int i = 0; i < 32; i += 8)
        tile[ty + i][tx] = src[(size_t)(k0 + ty + i) * GATES + n0 + tx];
    __syncthreads();
#pragma unroll
    for (int i = 0; i < 32; i += 8) {
        float v = tile[tx][ty + i];           // = src[k0+tx][n0+ty+i]
        size_t o = (size_t)(n0 + ty + i) * IN_DIM + k0 + tx;
        __nv_bfloat16 hi, lo;
        split_bf16(v, hi, lo);
        g_Wthi[o] = hi;
        g_Wtlo[o] = lo;
    }
}

// src [K=1024][N=4096] row-major -> g_Rt{hi,lo} [N][K] bf16 (transposed)
__global__ void convert_R(const float* __restrict__ src)
{
    __shared__ float tile[32][33];
    int n0 = blockIdx.x * 32, k0 = blockIdx.y * 32;
    int tx = threadIdx.x, ty = threadIdx.y;   // 32 x 8
#pragma unroll
    for (int i = 0; i < 32; i += 8)
        tile[ty + i][tx] = src[(size_t)(k0 + ty + i) * GATES + n0 + tx];
    __syncthreads();
#pragma unroll
    for (int i = 0; i < 32; i += 8) {
        float v = tile[tx][ty + i];
        size_t o = (size_t)(n0 + ty + i) * HID + k0 + tx;
        __nv_bfloat16 hi, lo;
        split_bf16(v, hi, lo);
        g_Rthi[o] = hi;
        g_Rtlo[o] = lo;
    }
}

// ---------------- wx GEMM: g_wx[M,N] = x@W + bias, split-bf16 mma ----------------
// M=32768, N=4096, K=1024. CTA tile 128x128, K-chunk 32, 8 warps (2m x 4n),
// warp tile 64x32 (4 m16 x 4 n8).
#define WXS 40   // smem k-stride (32 + 8 pad) in bf16 elems
__global__ __launch_bounds__(256) void wx_mma(const float* __restrict__ bias)
{
    __shared__ __align__(16) __nv_bfloat16 Ah[128 * WXS], Al[128 * WXS];
    __shared__ __align__(16) __nv_bfloat16 Bh[128 * WXS], Bl[128 * WXS];

    int tid  = threadIdx.x;
    int lane = tid & 31, w = tid >> 5;
    int g = lane >> 2, tq = lane & 3;
    size_t m0 = (size_t)blockIdx.y * 128;
    int n0 = blockIdx.x * 128;
    int wm = w & 1, wn = w >> 1;

    float acc[4][4][4];
#pragma unroll
    for (int mt = 0; mt < 4; mt++)
#pragma unroll
        for (int nt = 0; nt < 4; nt++)
#pragma unroll
            for (int r = 0; r < 4; r++) acc[mt][nt][r] = 0.f;

    for (int kc = 0; kc < 32; kc++) {
        int k0 = kc * 32;
#pragma unroll
        for (int rep = 0; rep < 2; rep++) {
            int id = tid + rep * 256;          // 0..511
            int row = id >> 2, seg = id & 3;   // 128 rows x 4 x 16B
            size_t asrc = (m0 + row) * IN_DIM + k0 + seg * 8;
            size_t bsrc = (size_t)(n0 + row) * IN_DIM + k0 + seg * 8;
            *(uint4*)&Ah[row * WXS + seg * 8] = *(const uint4*)&g_xhi[asrc];
            *(uint4*)&Al[row * WXS + seg * 8] = *(const uint4*)&g_xlo[asrc];
            *(uint4*)&Bh[row * WXS + seg * 8] = *(const uint4*)&g_Wthi[bsrc];
            *(uint4*)&Bl[row * WXS + seg * 8] = *(const uint4*)&g_Wtlo[bsrc];
        }
        __syncthreads();

#pragma unroll
        for (int ks = 0; ks < 2; ks++) {
            int ko = ks * 16;
            uint32_t bh[4][2], bl[4][2];
#pragma unroll
            for (int nt = 0; nt < 4; nt++) {
                int r = wn * 32 + nt * 8 + g;
                bh[nt][0] = *(const uint32_t*)&Bh[r * WXS + ko + 2 * tq];
                bh[nt][1] = *(const uint32_t*)&Bh[r * WXS + ko + 2 * tq + 8];
                bl[nt][0] = *(const uint32_t*)&Bl[r * WXS + ko + 2 * tq];
                bl[nt][1] = *(const uint32_t*)&Bl[r * WXS + ko + 2 * tq + 8];
            }
#pragma unroll
            for (int mt = 0; mt < 4; mt++) {
                int r0 = wm * 64 + mt * 16 + g, r1 = r0 + 8;
                uint32_t ah[4], al[4];
                ah[0] = *(const uint32_t*)&Ah[r0 * WXS + ko + 2 * tq];
                ah[1] = *(const uint32_t*)&Ah[r1 * WXS + ko + 2 * tq];
                ah[2] = *(const uint32_t*)&Ah[r0 * WXS + ko + 2 * tq + 8];
                ah[3] = *(const uint32_t*)&Ah[r1 * WXS + ko + 2 * tq + 8];
                al[0] = *(const uint32_t*)&Al[r0 * WXS + ko + 2 * tq];
                al[1] = *(const uint32_t*)&Al[r1 * WXS + ko + 2 * tq];
                al[2] = *(const uint32_t*)&Al[r0 * WXS + ko + 2 * tq + 8];
                al[3] = *(const uint32_t*)&Al[r1 * WXS + ko + 2 * tq + 8];
#pragma unroll
                for (int nt = 0; nt < 4; nt++) {
                    mma16816(acc[mt][nt], ah, bh[nt]);
                    mma16816(acc[mt][nt], ah, bl[nt]);
                    mma16816(acc[mt][nt], al, bh[nt]);
                }
            }
        }
        __syncthreads();
    }

#pragma unroll
    for (int mt = 0; mt < 4; mt++) {
        size_t row = m0 + wm * 64 + mt * 16 + g;
#pragma unroll
        for (int nt = 0; nt < 4; nt++) {
            int col = n0 + wn * 32 + nt * 8 + 2 * tq;
            g_wx[row * GATES + col]           = acc[mt][nt][0] + bias[col];
            g_wx[row * GATES + col + 1]       = acc[mt][nt][1] + bias[col + 1];
            g_wx[(row + 8) * GATES + col]     = acc[mt][nt][2] + bias[col];
            g_wx[(row + 8) * GATES + col + 1] = acc[mt][nt][3] + bias[col + 1];
        }
    }
}

// ---------------- fused LSTM step (tensor core) ----------------
// v[64,4096] = wx[t] + h_prev @ R. Grid 128: CTA owns 8 h-cols x 4 gates
// (n8 tile nt == gate nt, col group hc0..hc0+7). 4 warps, warp = 16 batch rows.
// C-fragment => all 4 gates for one (b,col) land in the same lane: no shuffles.
#define STS 72   // smem k-stride (64 + 8 pad) in bf16 elems
__global__ __launch_bounds__(128) void lstm_step_mma(int t, float* __restrict__ out_base)
{
    __shared__ __align__(16) __nv_bfloat16 Hh[64 * STS], Hl[64 * STS];
    __shared__ __align__(16) __nv_bfloat16 Rh[32 * STS], Rl[32 * STS];

    int tid  = threadIdx.x;
    int lane = tid & 31, w = tid >> 5;
    int g = lane >> 2, tq = lane & 3;
    int hc0 = blockIdx.x * 8;

    float acc[4][4];
#pragma unroll
    for (int nt = 0; nt < 4; nt++)
#pragma unroll
        for (int r = 0; r < 4; r++) acc[nt][r] = 0.f;

    if (t > 0) {
        int pb = (t - 1) & 1;
        const __nv_bfloat16* hhi = g_hhi[pb];
        const __nv_bfloat16* hlo = g_hlo[pb];

        for (int kc = 0; kc < 16; kc++) {
            int k0 = kc * 64;
            // stage h: 64 rows x 64 k (8 x 16B segs per row)
#pragma unroll
            for (int rep = 0; rep < 4; rep++) {
                int id = tid + rep * 128;       // 0..511
                int row = id >> 3, seg = id & 7;
                size_t src = (size_t)row * HID + k0 + seg * 8;
                *(uint4*)&Hh[row * STS + seg * 8] = *(const uint4*)&hhi[src];
                *(uint4*)&Hl[row * STS + seg * 8] = *(const uint4*)&hlo[src];
            }
            // stage R: 32 rows (gate*8+c8) x 64 k
#pragma unroll
            for (int rep = 0; rep < 2; rep++) {
                int id = tid + rep * 128;       // 0..255
                int row = id >> 3, seg = id & 7;
                int gate = row >> 3, c8 = row & 7;
                size_t src = (size_t)(gate * HID + hc0 + c8) * HID + k0 + seg * 8;
                *(uint4*)&Rh[row * STS + seg * 8] = *(const uint4*)&g_Rthi[src];
                *(uint4*)&Rl[row * STS + seg * 8] = *(const uint4*)&g_Rtlo[src];
            }
            __syncthreads();

#pragma unroll
            for (int ks = 0; ks < 4; ks++) {
                int ko = ks * 16;
                int r0 = w * 16 + g, r1 = r0 + 8;
                uint32_t ah[4], al[4];
                ah[0] = *(const uint32_t*)&Hh[r0 * STS + ko + 2 * tq];
                ah[1] = *(const uint32_t*)&Hh[r1 * STS + ko + 2 * tq];
                ah[2] = *(const uint32_t*)&Hh[r0 * STS + ko + 2 * tq + 8];
                ah[3] = *(const uint32_t*)&Hh[r1 * STS + ko + 2 * tq + 8];
                al[0] = *(const uint32_t*)&Hl[r0 * STS + ko + 2 * tq];
                al[1] = *(const uint32_t*)&Hl[r1 * STS + ko + 2 * tq];
                al[2] = *(const uint32_t*)&Hl[r0 * STS + ko + 2 * tq + 8];
                al[3] = *(const uint32_t*)&Hl[r1 * STS + ko + 2 * tq + 8];
#pragma unroll
                for (int nt = 0; nt < 4; nt++) {
                    int rr = nt * 8 + g;
                    uint32_t bh[2], bl[2];
                    bh[0] = *(const uint32_t*)&Rh[rr * STS + ko + 2 * tq];
                    bh[1] = *(const uint32_t*)&Rh[rr * STS + ko + 2 * tq + 8];
                    bl[0] = *(const uint32_t*)&Rl[rr * STS + ko + 2 * tq];
                    bl[1] = *(const uint32_t*)&Rl[rr * STS + ko + 2 * tq + 8];
                    mma16816(acc[nt], ah, bh);
                    mma16816(acc[nt], ah, bl);
                    mma16816(acc[nt], al, bh);
                }
            }
            __syncthreads();
        }
    }

    // epilogue: gates, cell update, h writes (fp32 + bf16 hi/lo ping-pong)
    const float* wx_t = g_wx + (size_t)t * BATCH * GATES;
    float* h_out = out_base + (size_t)t * BATCH * HID;
    int cb = t & 1;
#pragma unroll
    for (int j = 0; j < 4; j++) {
        int brow = w * 16 + g + ((j >> 1) * 8);
        int cofs = 2 * tq + (j & 1);
        int col  = hc0 + cofs;
        const float* wb = wx_t + (size_t)brow * GATES;
        float vi = acc[0][j] + wb[0 * HID + col];
        float vg = acc[1][j] + wb[1 * HID + col];
        float vf = acc[2][j] + wb[2 * HID + col];
        float vo = acc[3][j] + wb[3 * HID + col];
        float ii = 1.f / (1.f + expf(-vi));
        float gg = tanhf(vg);
        float ff = 1.f / (1.f + expf(-vf));
        float oo = 1.f / (1.f + expf(-vo));
        int idx = brow * HID + col;
        float cp = (t > 0) ? g_c[idx] : 0.f;
        float cn = ff * cp + ii * gg;
        g_c[idx] = cn;
        float h = oo * tanhf(cn);
        h_out[idx] = h;
        __nv_bfloat16 hi, lo;
        split_bf16(h, hi, lo);
        g_hhi[cb][idx] = hi;
        g_hlo[cb][idx] = lo;
    }
}

// ---------------- epilogue: h_last, c_last ----------------
__global__ void finalize(float* __restrict__ out)
{
    int i = blockIdx.x * blockDim.x + threadIdx.x;
    if (i < BATCH * HID) {
        size_t base = (size_t)T_STEPS * BATCH * HID;
        out[base + i] = out[(size_t)(T_STEPS - 1) * BATCH * HID + i];
        out[base + BATCH * HID + i] = g_c[i];
    }
}

extern "C" void kernel_launch(void* const* d_in, const int* in_sizes, int n_in,
                              void* d_out, int out_size)
{
    const float* x    = (const float*)d_in[0];
    const float* Wk   = (const float*)d_in[1];
    const float* Rk   = (const float*)d_in[2];
    const float* bias = (const float*)d_in[3];
    float* out = (float*)d_out;

    size_t nx = (size_t)T_STEPS * BATCH * IN_DIM;
    convert_x<<<(unsigned)((nx + 255) / 256), 256>>>(x);
    convert_W<<<dim3(GATES / 32, IN_DIM / 32), dim3(32, 8)>>>(Wk);
    convert_R<<<dim3(GATES / 32, HID / 32), dim3(32, 8)>>>(Rk);

    wx_mma<<<dim3(GATES / 128, (T_STEPS * BATCH) / 128), 256>>>(bias);

    for (int t = 0; t < T_STEPS; t++)
        lstm_step_mma<<<HID / 8, 128>>>(t, out);

    finalize<<<(BATCH * HID + 255) / 256, 256>>>(out);
}

// round 6
// speedup vs baseline: 1.0020x; 1.0020x over previous
#include <cuda_runtime.h>
#include <cuda_bf16.h>
#include <math.h>
#include <stdint.h>

#define T_STEPS 512
#define BATCH   64
#define IN_DIM  1024
#define HID     1024
#define GATES   4096   // 4*HID, gate order i,g,f,o

// ---------------- device scratch ----------------
__device__ float g_wx[(size_t)T_STEPS * BATCH * GATES];   // 512 MB
__device__ float g_c[BATCH * HID];

__device__ __nv_bfloat16 g_xhi[(size_t)T_STEPS * BATCH * IN_DIM];
__device__ __nv_bfloat16 g_xlo[(size_t)T_STEPS * BATCH * IN_DIM];
__device__ __nv_bfloat16 g_Wthi[(size_t)GATES * IN_DIM];   // transposed [N][K]
__device__ __nv_bfloat16 g_Wtlo[(size_t)GATES * IN_DIM];
__device__ __nv_bfloat16 g_Rthi[(size_t)GATES * HID];      // transposed [N][K]
__device__ __nv_bfloat16 g_Rtlo[(size_t)GATES * HID];
__device__ __nv_bfloat16 g_hhi[2][BATCH * HID];            // ping-pong h in bf16 hi/lo
__device__ __nv_bfloat16 g_hlo[2][BATCH * HID];

// ---------------- mma.m16n8k16 bf16 helper ----------------
// Fragment layout (g = lane>>2, t = lane&3):
//  A row-major 16x16: a0=A[g][2t..], a1=A[g+8][2t..], a2=A[g][2t+8..], a3=A[g+8][2t+8..]
//  B col-major 16x8 stored here as Bt[n][k]: b0=Bt[g][2t..], b1=Bt[g][2t+8..]
//  C 16x8 f32: c0=C[g][2t], c1=C[g][2t+1], c2=C[g+8][2t], c3=C[g+8][2t+1]
__device__ __forceinline__ void mma16816(float* c, const uint32_t* a, const uint32_t* b)
{
    asm volatile(
        "mma.sync.aligned.m16n8k16.row.col.f32.bf16.bf16.f32 "
        "{%0,%1,%2,%3}, {%4,%5,%6,%7}, {%8,%9}, {%0,%1,%2,%3};"
        : "+f"(c[0]), "+f"(c[1]), "+f"(c[2]), "+f"(c[3])
        : "r"(a[0]), "r"(a[1]), "r"(a[2]), "r"(a[3]), "r"(b[0]), "r"(b[1]));
}

__device__ __forceinline__ void split_bf16(float v, __nv_bfloat16& hi, __nv_bfloat16& lo)
{
    hi = __float2bfloat16_rn(v);
    lo = __float2bfloat16_rn(v - __bfloat162float(hi));
}

// ---------------- conversion kernels ----------------
// All write targets are referenced directly from DEVICE code (never passed as
// kernel args from host — __device__ symbols are invalid host-side).
__global__ void convert_x(const float* __restrict__ x)
{
    size_t i = (size_t)blockIdx.x * blockDim.x + threadIdx.x;
    if (i < (size_t)T_STEPS * BATCH * IN_DIM) {
        __nv_bfloat16 hi, lo;
        split_bf16(x[i], hi, lo);
        g_xhi[i] = hi;
        g_xlo[i] = lo;
    }
}

// src [K=1024][N=4096] row-major -> g_Wt{hi,lo} [N][K] bf16 (transposed)
__global__ void convert_W(const float* __restrict__ src)
{
    __shared__ float tile[32][33];
    int n0 = blockIdx.x * 32, k0 = blockIdx.y * 32;
    int tx = threadIdx.x, ty = threadIdx.y;   // 32 x 8
#pragma unroll
    for (int i = 0; i < 32; i += 8)
        tile[ty + i][tx] = src[(size_t)(k0 + ty + i) * GATES + n0 + tx];
    __syncthreads();
#pragma unroll
    for (int i = 0; i < 32; i += 8) {
        float v = tile[tx][ty + i];           // = src[k0+tx][n0+ty+i]
        size_t o = (size_t)(n0 + ty + i) * IN_DIM + k0 + tx;
        __nv_bfloat16 hi, lo;
        split_bf16(v, hi, lo);
        g_Wthi[o] = hi;
        g_Wtlo[o] = lo;
    }
}

// src [K=1024][N=4096] row-major -> g_Rt{hi,lo} [N][K] bf16 (transposed)
__global__ void convert_R(const float* __restrict__ src)
{
    __shared__ float tile[32][33];
    int n0 = blockIdx.x * 32, k0 = blockIdx.y * 32;
    int tx = threadIdx.x, ty = threadIdx.y;   // 32 x 8
#pragma unroll
    for (int i = 0; i < 32; i += 8)
        tile[ty + i][tx] = src[(size_t)(k0 + ty + i) * GATES + n0 + tx];
    __syncthreads();
#pragma unroll
    for (int i = 0; i < 32; i += 8) {
        float v = tile[tx][ty + i];
        size_t o = (size_t)(n0 + ty + i) * HID + k0 + tx;
        __nv_bfloat16 hi, lo;
        split_bf16(v, hi, lo);
        g_Rthi[o] = hi;
        g_Rtlo[o] = lo;
    }
}

// ---------------- wx GEMM: g_wx[M,N] = x@W + bias, split-bf16 mma ----------------
// M=32768, N=4096, K=1024. CTA tile 128x128, K-chunk 32, 8 warps (2m x 4n),
// warp tile 64x32 (4 m16 x 4 n8).
#define WXS 40   // smem k-stride (32 + 8 pad) in bf16 elems
__global__ __launch_bounds__(256) void wx_mma(const float* __restrict__ bias)
{
    __shared__ __align__(16) __nv_bfloat16 Ah[128 * WXS], Al[128 * WXS];
    __shared__ __align__(16) __nv_bfloat16 Bh[128 * WXS], Bl[128 * WXS];

    int tid  = threadIdx.x;
    int lane = tid & 31, w = tid >> 5;
    int g = lane >> 2, tq = lane & 3;
    size_t m0 = (size_t)blockIdx.y * 128;
    int n0 = blockIdx.x * 128;
    int wm = w & 1, wn = w >> 1;

    float acc[4][4][4];
#pragma unroll
    for (int mt = 0; mt < 4; mt++)
#pragma unroll
        for (int nt = 0; nt < 4; nt++)
#pragma unroll
            for (int r = 0; r < 4; r++) acc[mt][nt][r] = 0.f;

    for (int kc = 0; kc < 32; kc++) {
        int k0 = kc * 32;
#pragma unroll
        for (int rep = 0; rep < 2; rep++) {
            int id = tid + rep * 256;          // 0..511
            int row = id >> 2, seg = id & 3;   // 128 rows x 4 x 16B
            size_t asrc = (m0 + row) * IN_DIM + k0 + seg * 8;
            size_t bsrc = (size_t)(n0 + row) * IN_DIM + k0 + seg * 8;
            *(uint4*)&Ah[row * WXS + seg * 8] = *(const uint4*)&g_xhi[asrc];
            *(uint4*)&Al[row * WXS + seg * 8] = *(const uint4*)&g_xlo[asrc];
            *(uint4*)&Bh[row * WXS + seg * 8] = *(const uint4*)&g_Wthi[bsrc];
            *(uint4*)&Bl[row * WXS + seg * 8] = *(const uint4*)&g_Wtlo[bsrc];
        }
        __syncthreads();

#pragma unroll
        for (int ks = 0; ks < 2; ks++) {
            int ko = ks * 16;
            uint32_t bh[4][2], bl[4][2];
#pragma unroll
            for (int nt = 0; nt < 4; nt++) {
                int r = wn * 32 + nt * 8 + g;
                bh[nt][0] = *(const uint32_t*)&Bh[r * WXS + ko + 2 * tq];
                bh[nt][1] = *(const uint32_t*)&Bh[r * WXS + ko + 2 * tq + 8];
                bl[nt][0] = *(const uint32_t*)&Bl[r * WXS + ko + 2 * tq];
                bl[nt][1] = *(const uint32_t*)&Bl[r * WXS + ko + 2 * tq + 8];
            }
#pragma unroll
            for (int mt = 0; mt < 4; mt++) {
                int r0 = wm * 64 + mt * 16 + g, r1 = r0 + 8;
                uint32_t ah[4], al[4];
                ah[0] = *(const uint32_t*)&Ah[r0 * WXS + ko + 2 * tq];
                ah[1] = *(const uint32_t*)&Ah[r1 * WXS + ko + 2 * tq];
                ah[2] = *(const uint32_t*)&Ah[r0 * WXS + ko + 2 * tq + 8];
                ah[3] = *(const uint32_t*)&Ah[r1 * WXS + ko + 2 * tq + 8];
                al[0] = *(const uint32_t*)&Al[r0 * WXS + ko + 2 * tq];
                al[1] = *(const uint32_t*)&Al[r1 * WXS + ko + 2 * tq];
                al[2] = *(const uint32_t*)&Al[r0 * WXS + ko + 2 * tq + 8];
                al[3] = *(const uint32_t*)&Al[r1 * WXS + ko + 2 * tq + 8];
#pragma unroll
                for (int nt = 0; nt < 4; nt++) {
                    mma16816(acc[mt][nt], ah, bh[nt]);
                    mma16816(acc[mt][nt], ah, bl[nt]);
                    mma16816(acc[mt][nt], al, bh[nt]);
                }
            }
        }
        __syncthreads();
    }

#pragma unroll
    for (int mt = 0; mt < 4; mt++) {
        size_t row = m0 + wm * 64 + mt * 16 + g;
#pragma unroll
        for (int nt = 0; nt < 4; nt++) {
            int col = n0 + wn * 32 + nt * 8 + 2 * tq;
            g_wx[row * GATES + col]           = acc[mt][nt][0] + bias[col];
            g_wx[row * GATES + col + 1]       = acc[mt][nt][1] + bias[col + 1];
            g_wx[(row + 8) * GATES + col]     = acc[mt][nt][2] + bias[col];
            g_wx[(row + 8) * GATES + col + 1] = acc[mt][nt][3] + bias[col + 1];
        }
    }
}

// ---------------- fused LSTM step (tensor core) ----------------
// v[64,4096] = wx[t] + h_prev @ R. Grid 128: CTA owns 8 h-cols x 4 gates
// (n8 tile nt == gate nt, col group hc0..hc0+7). 4 warps, warp = 16 batch rows.
// C-fragment => all 4 gates for one (b,col) land in the same lane: no shuffles.
#define STS 72   // smem k-stride (64 + 8 pad) in bf16 elems
__global__ __launch_bounds__(128) void lstm_step_mma(int t, float* __restrict__ out_base)
{
    __shared__ __align__(16) __nv_bfloat16 Hh[64 * STS], Hl[64 * STS];
    __shared__ __align__(16) __nv_bfloat16 Rh[32 * STS], Rl[32 * STS];

    int tid  = threadIdx.x;
    int lane = tid & 31, w = tid >> 5;
    int g = lane >> 2, tq = lane & 3;
    int hc0 = blockIdx.x * 8;

    float acc[4][4];
#pragma unroll
    for (int nt = 0; nt < 4; nt++)
#pragma unroll
        for (int r = 0; r < 4; r++) acc[nt][r] = 0.f;

    if (t > 0) {
        int pb = (t - 1) & 1;
        const __nv_bfloat16* hhi = g_hhi[pb];
        const __nv_bfloat16* hlo = g_hlo[pb];

        for (int kc = 0; kc < 16; kc++) {
            int k0 = kc * 64;
            // stage h: 64 rows x 64 k (8 x 16B segs per row)
#pragma unroll
            for (int rep = 0; rep < 4; rep++) {
                int id = tid + rep * 128;       // 0..511
                int row = id >> 3, seg = id & 7;
                size_t src = (size_t)row * HID + k0 + seg * 8;
                *(uint4*)&Hh[row * STS + seg * 8] = *(const uint4*)&hhi[src];
                *(uint4*)&Hl[row * STS + seg * 8] = *(const uint4*)&hlo[src];
            }
            // stage R: 32 rows (gate*8+c8) x 64 k
#pragma unroll
            for (int rep = 0; rep < 2; rep++) {
                int id = tid + rep * 128;       // 0..255
                int row = id >> 3, seg = id & 7;
                int gate = row >> 3, c8 = row & 7;
                size_t src = (size_t)(gate * HID + hc0 + c8) * HID + k0 + seg * 8;
                *(uint4*)&Rh[row * STS + seg * 8] = *(const uint4*)&g_Rthi[src];
                *(uint4*)&Rl[row * STS + seg * 8] = *(const uint4*)&g_Rtlo[src];
            }
            __syncthreads();

#pragma unroll
            for (int ks = 0; ks < 4; ks++) {
                int ko = ks * 16;
                int r0 = w * 16 + g, r1 = r0 + 8;
                uint32_t ah[4], al[4];
                ah[0] = *(const uint32_t*)&Hh[r0 * STS + ko + 2 * tq];
                ah[1] = *(const uint32_t*)&Hh[r1 * STS + ko + 2 * tq];
                ah[2] = *(const uint32_t*)&Hh[r0 * STS + ko + 2 * tq + 8];
                ah[3] = *(const uint32_t*)&Hh[r1 * STS + ko + 2 * tq + 8];
                al[0] = *(const uint32_t*)&Hl[r0 * STS + ko + 2 * tq];
                al[1] = *(const uint32_t*)&Hl[r1 * STS + ko + 2 * tq];
                al[2] = *(const uint32_t*)&Hl[r0 * STS + ko + 2 * tq + 8];
                al[3] = *(const uint32_t*)&Hl[r1 * STS + ko + 2 * tq + 8];
#pragma unroll
                for (int nt = 0; nt < 4; nt++) {
                    int rr = nt * 8 + g;
                    uint32_t bh[2], bl[2];
                    bh[0] = *(const uint32_t*)&Rh[rr * STS + ko + 2 * tq];
                    bh[1] = *(const uint32_t*)&Rh[rr * STS + ko + 2 * tq + 8];
                    bl[0] = *(const uint32_t*)&Rl[rr * STS + ko + 2 * tq];
                    bl[1] = *(const uint32_t*)&Rl[rr * STS + ko + 2 * tq + 8];
                    mma16816(acc[nt], ah, bh);
                    mma16816(acc[nt], ah, bl);
                    mma16816(acc[nt], al, bh);
                }
            }
            __syncthreads();
        }
    }

    // epilogue: gates, cell update, h writes (fp32 + bf16 hi/lo ping-pong)
    const float* wx_t = g_wx + (size_t)t * BATCH * GATES;
    float* h_out = out_base + (size_t)t * BATCH * HID;
    int cb = t & 1;
#pragma unroll
    for (int j = 0; j < 4; j++) {
        int brow = w * 16 + g + ((j >> 1) * 8);
        int cofs = 2 * tq + (j & 1);
        int col  = hc0 + cofs;
        const float* wb = wx_t + (size_t)brow * GATES;
        float vi = acc[0][j] + wb[0 * HID + col];
        float vg = acc[1][j] + wb[1 * HID + col];
        float vf = acc[2][j] + wb[2 * HID + col];
        float vo = acc[3][j] + wb[3 * HID + col];
        float ii = 1.f / (1.f + expf(-vi));
        float gg = tanhf(vg);
        float ff = 1.f / (1.f + expf(-vf));
        float oo = 1.f / (1.f + expf(-vo));
        int idx = brow * HID + col;
        float cp = (t > 0) ? g_c[idx] : 0.f;
        float cn = ff * cp + ii * gg;
        g_c[idx] = cn;
        float h = oo * tanhf(cn);
        h_out[idx] = h;
        __nv_bfloat16 hi, lo;
        split_bf16(h, hi, lo);
        g_hhi[cb][idx] = hi;
        g_hlo[cb][idx] = lo;
    }
}

// ---------------- epilogue: h_last, c_last ----------------
__global__ void finalize(float* __restrict__ out)
{
    int i = blockIdx.x * blockDim.x + threadIdx.x;
    if (i < BATCH * HID) {
        size_t base = (size_t)T_STEPS * BATCH * HID;
        out[base + i] = out[(size_t)(T_STEPS - 1) * BATCH * HID + i];
        out[base + BATCH * HID + i] = g_c[i];
    }
}

extern "C" void kernel_launch(void* const* d_in, const int* in_sizes, int n_in,
                              void* d_out, int out_size)
{
    const float* x    = (const float*)d_in[0];
    const float* Wk   = (const float*)d_in[1];
    const float* Rk   = (const float*)d_in[2];
    const float* bias = (const float*)d_in[3];
    float* out = (float*)d_out;

    size_t nx = (size_t)T_STEPS * BATCH * IN_DIM;
    convert_x<<<(unsigned)((nx + 255) / 256), 256>>>(x);
    convert_W<<<dim3(GATES / 32, IN_DIM / 32), dim3(32, 8)>>>(Wk);
    convert_R<<<dim3(GATES / 32, HID / 32), dim3(32, 8)>>>(Rk);

    wx_mma<<<dim3(GATES / 128, (T_STEPS * BATCH) / 128), 256>>>(bias);

    for (int t = 0; t < T_STEPS; t++)
        lstm_step_mma<<<HID / 8, 128>>>(t, out);

    finalize<<<(BATCH * HID + 255) / 256, 256>>>(out);
}

// round 7
// speedup vs baseline: 1.4115x; 1.4087x over previous
#include <cuda_runtime.h>
#include <cuda_bf16.h>
#include <math.h>
#include <stdint.h>

#define T_STEPS 512
#define BATCH   64
#define IN_DIM  1024
#define HID     1024
#define GATES   4096   // 4*HID, gate order i,g,f,o
#define NCTA    128

// ---------------- device scratch ----------------
__device__ float g_wx[(size_t)T_STEPS * BATCH * GATES];   // 512 MB
__device__ float g_c[BATCH * HID];
__device__ volatile unsigned g_bar;                       // zero-init; self-resets

__device__ __nv_bfloat16 g_xhi[(size_t)T_STEPS * BATCH * IN_DIM];
__device__ __nv_bfloat16 g_xlo[(size_t)T_STEPS * BATCH * IN_DIM];
__device__ __nv_bfloat16 g_Wthi[(size_t)GATES * IN_DIM];   // transposed [N][K]
__device__ __nv_bfloat16 g_Wtlo[(size_t)GATES * IN_DIM];
__device__ __nv_bfloat16 g_Rthi[(size_t)GATES * HID];      // transposed [N][K]
__device__ __nv_bfloat16 g_Rtlo[(size_t)GATES * HID];
__device__ __nv_bfloat16 g_hhi[2][BATCH * HID];            // ping-pong h bf16 hi/lo
__device__ __nv_bfloat16 g_hlo[2][BATCH * HID];

// ---------------- mma.m16n8k16 bf16 helper ----------------
__device__ __forceinline__ void mma16816(float* c, const uint32_t* a, const uint32_t* b)
{
    asm volatile(
        "mma.sync.aligned.m16n8k16.row.col.f32.bf16.bf16.f32 "
        "{%0,%1,%2,%3}, {%4,%5,%6,%7}, {%8,%9}, {%0,%1,%2,%3};"
        : "+f"(c[0]), "+f"(c[1]), "+f"(c[2]), "+f"(c[3])
        : "r"(a[0]), "r"(a[1]), "r"(a[2]), "r"(a[3]), "r"(b[0]), "r"(b[1]));
}

__device__ __forceinline__ void split_bf16(float v, __nv_bfloat16& hi, __nv_bfloat16& lo)
{
    hi = __float2bfloat16_rn(v);
    lo = __float2bfloat16_rn(v - __bfloat162float(hi));
}

// L2-only 16B load (L1 is NOT coherent across SMs inside the persistent kernel)
__device__ __forceinline__ uint4 ldcg16(const void* p)
{
    uint4 v;
    asm volatile("ld.global.cg.v4.u32 {%0,%1,%2,%3}, [%4];"
                 : "=r"(v.x), "=r"(v.y), "=r"(v.z), "=r"(v.w) : "l"(p));
    return v;
}

// ---------------- conversion kernels ----------------
__global__ void convert_x(const float* __restrict__ x)
{
    size_t i = (size_t)blockIdx.x * blockDim.x + threadIdx.x;
    if (i < (size_t)T_STEPS * BATCH * IN_DIM) {
        __nv_bfloat16 hi, lo;
        split_bf16(x[i], hi, lo);
        g_xhi[i] = hi;
        g_xlo[i] = lo;
    }
}

__global__ void convert_W(const float* __restrict__ src)
{
    __shared__ float tile[32][33];
    int n0 = blockIdx.x * 32, k0 = blockIdx.y * 32;
    int tx = threadIdx.x, ty = threadIdx.y;
#pragma unroll
    for (int i = 0; i < 32; i += 8)
        tile[ty + i][tx] = src[(size_t)(k0 + ty + i) * GATES + n0 + tx];
    __syncthreads();
#pragma unroll
    for (int i = 0; i < 32; i += 8) {
        float v = tile[tx][ty + i];
        size_t o = (size_t)(n0 + ty + i) * IN_DIM + k0 + tx;
        __nv_bfloat16 hi, lo;
        split_bf16(v, hi, lo);
        g_Wthi[o] = hi;
        g_Wtlo[o] = lo;
    }
}

__global__ void convert_R(const float* __restrict__ src)
{
    __shared__ float tile[32][33];
    int n0 = blockIdx.x * 32, k0 = blockIdx.y * 32;
    int tx = threadIdx.x, ty = threadIdx.y;
#pragma unroll
    for (int i = 0; i < 32; i += 8)
        tile[ty + i][tx] = src[(size_t)(k0 + ty + i) * GATES + n0 + tx];
    __syncthreads();
#pragma unroll
    for (int i = 0; i < 32; i += 8) {
        float v = tile[tx][ty + i];
        size_t o = (size_t)(n0 + ty + i) * HID + k0 + tx;
        __nv_bfloat16 hi, lo;
        split_bf16(v, hi, lo);
        g_Rthi[o] = hi;
        g_Rtlo[o] = lo;
    }
}

// ---------------- wx GEMM (unchanged from R5/R6 passing version) ----------------
#define WXS 40
__global__ __launch_bounds__(256) void wx_mma(const float* __restrict__ bias)
{
    __shared__ __align__(16) __nv_bfloat16 Ah[128 * WXS], Al[128 * WXS];
    __shared__ __align__(16) __nv_bfloat16 Bh[128 * WXS], Bl[128 * WXS];

    int tid  = threadIdx.x;
    int lane = tid & 31, w = tid >> 5;
    int g = lane >> 2, tq = lane & 3;
    size_t m0 = (size_t)blockIdx.y * 128;
    int n0 = blockIdx.x * 128;
    int wm = w & 1, wn = w >> 1;

    float acc[4][4][4];
#pragma unroll
    for (int mt = 0; mt < 4; mt++)
#pragma unroll
        for (int nt = 0; nt < 4; nt++)
#pragma unroll
            for (int r = 0; r < 4; r++) acc[mt][nt][r] = 0.f;

    for (int kc = 0; kc < 32; kc++) {
        int k0 = kc * 32;
#pragma unroll
        for (int rep = 0; rep < 2; rep++) {
            int id = tid + rep * 256;
            int row = id >> 2, seg = id & 3;
            size_t asrc = (m0 + row) * IN_DIM + k0 + seg * 8;
            size_t bsrc = (size_t)(n0 + row) * IN_DIM + k0 + seg * 8;
            *(uint4*)&Ah[row * WXS + seg * 8] = *(const uint4*)&g_xhi[asrc];
            *(uint4*)&Al[row * WXS + seg * 8] = *(const uint4*)&g_xlo[asrc];
            *(uint4*)&Bh[row * WXS + seg * 8] = *(const uint4*)&g_Wthi[bsrc];
            *(uint4*)&Bl[row * WXS + seg * 8] = *(const uint4*)&g_Wtlo[bsrc];
        }
        __syncthreads();

#pragma unroll
        for (int ks = 0; ks < 2; ks++) {
            int ko = ks * 16;
            uint32_t bh[4][2], bl[4][2];
#pragma unroll
            for (int nt = 0; nt < 4; nt++) {
                int r = wn * 32 + nt * 8 + g;
                bh[nt][0] = *(const uint32_t*)&Bh[r * WXS + ko + 2 * tq];
                bh[nt][1] = *(const uint32_t*)&Bh[r * WXS + ko + 2 * tq + 8];
                bl[nt][0] = *(const uint32_t*)&Bl[r * WXS + ko + 2 * tq];
                bl[nt][1] = *(const uint32_t*)&Bl[r * WXS + ko + 2 * tq + 8];
            }
#pragma unroll
            for (int mt = 0; mt < 4; mt++) {
                int r0 = wm * 64 + mt * 16 + g, r1 = r0 + 8;
                uint32_t ah[4], al[4];
                ah[0] = *(const uint32_t*)&Ah[r0 * WXS + ko + 2 * tq];
                ah[1] = *(const uint32_t*)&Ah[r1 * WXS + ko + 2 * tq];
                ah[2] = *(const uint32_t*)&Ah[r0 * WXS + ko + 2 * tq + 8];
                ah[3] = *(const uint32_t*)&Ah[r1 * WXS + ko + 2 * tq + 8];
                al[0] = *(const uint32_t*)&Al[r0 * WXS + ko + 2 * tq];
                al[1] = *(const uint32_t*)&Al[r1 * WXS + ko + 2 * tq];
                al[2] = *(const uint32_t*)&Al[r0 * WXS + ko + 2 * tq + 8];
                al[3] = *(const uint32_t*)&Al[r1 * WXS + ko + 2 * tq + 8];
#pragma unroll
                for (int nt = 0; nt < 4; nt++) {
                    mma16816(acc[mt][nt], ah, bh[nt]);
                    mma16816(acc[mt][nt], ah, bl[nt]);
                    mma16816(acc[mt][nt], al, bh[nt]);
                }
            }
        }
        __syncthreads();
    }

#pragma unroll
    for (int mt = 0; mt < 4; mt++) {
        size_t row = m0 + wm * 64 + mt * 16 + g;
#pragma unroll
        for (int nt = 0; nt < 4; nt++) {
            int col = n0 + wn * 32 + nt * 8 + 2 * tq;
            g_wx[row * GATES + col]           = acc[mt][nt][0] + bias[col];
            g_wx[row * GATES + col + 1]       = acc[mt][nt][1] + bias[col + 1];
            g_wx[(row + 8) * GATES + col]     = acc[mt][nt][2] + bias[col];
            g_wx[(row + 8) * GATES + col + 1] = acc[mt][nt][3] + bias[col + 1];
        }
    }
}

// ---------------- persistent LSTM recurrence ----------------
// 128 CTAs (1/SM), 256 threads. CTA owns 8 h-cols x 4 gates for all steps.
// R slice resident in smem. Warps 0-3: k in [0,512); warps 4-7: k in [512,1024).
// fp32 partials reduced through smem; shuffle-free gate layout preserved.
#define RSTR 1032                 // R smem k-stride (1024 + 8 pad)
#define HSTR 72                   // H chunk k-stride (64 + 8 pad)
#define HSZ  (64 * HSTR)          // elems per H chunk buffer
#define SMEM_PERS (2 * 32 * RSTR * 2 + 8 * HSZ * 2)   // 132096 + 73728 = 205824 B

__global__ __launch_bounds__(256) void lstm_persistent(float* __restrict__ out_base)
{
    extern __shared__ __align__(16) unsigned char smem_raw[];
    __nv_bfloat16* Rh = (__nv_bfloat16*)smem_raw;
    __nv_bfloat16* Rl = Rh + 32 * RSTR;
    __nv_bfloat16* Hbase = Rl + 32 * RSTR;   // 8 buffers: [isLo*4 + grp*2 + buf]
    float* Red = (float*)Hbase;              // reduction scratch (overlaps H, fenced by syncs)

    const int tid  = threadIdx.x;
    const int lane = tid & 31, w = tid >> 5;
    const int g = lane >> 2, tq = lane & 3;
    const int grp = w >> 2, wm = w & 3;
    const int hc0 = blockIdx.x * 8;

    // Load R slice into smem once: rows 0..31 = gate*8 + c8, k 0..1023
    for (int rep = 0; rep < 16; rep++) {
        int id = rep * 256 + tid;
        int row = id >> 7, seg = id & 127;
        size_t src = (size_t)((row >> 3) * HID + hc0 + (row & 7)) * HID + seg * 8;
        *(uint4*)&Rh[row * RSTR + seg * 8] = *(const uint4*)&g_Rthi[src];
        *(uint4*)&Rl[row * RSTR + seg * 8] = *(const uint4*)&g_Rtlo[src];
    }
    __syncthreads();

    for (int t = 0; t < T_STEPS; t++) {
        float acc[4][4];
#pragma unroll
        for (int nt = 0; nt < 4; nt++)
#pragma unroll
            for (int r = 0; r < 4; r++) acc[nt][r] = 0.f;

        if (t > 0) {
            const __nv_bfloat16* hhi = g_hhi[(t - 1) & 1];
            const __nv_bfloat16* hlo = g_hlo[(t - 1) & 1];

            // stage kc=0 into buf 0 (L2-only loads: cross-CTA data)
#pragma unroll
            for (int rep = 0; rep < 8; rep++) {
                int arr = rep >> 1;                       // 0..3
                int idx = (rep & 1) * 256 + tid;          // 0..511
                int row = idx >> 3, seg = idx & 7;
                int isLo = arr >> 1, grpA = arr & 1;
                const __nv_bfloat16* src = (isLo ? hlo : hhi)
                    + (size_t)row * HID + grpA * 512 + seg * 8;
                __nv_bfloat16* dst = Hbase + (isLo * 4 + grpA * 2) * HSZ
                    + row * HSTR + seg * 8;
                *(uint4*)dst = ldcg16(src);
            }
            __syncthreads();

            for (int kc = 0; kc < 8; kc++) {
                int cur = kc & 1;
                uint4 pf[8];
                if (kc < 7) {                              // prefetch next chunk
#pragma unroll
                    for (int rep = 0; rep < 8; rep++) {
                        int arr = rep >> 1;
                        int idx = (rep & 1) * 256 + tid;
                        int row = idx >> 3, seg = idx & 7;
                        int isLo = arr >> 1, grpA = arr & 1;
                        pf[rep] = ldcg16((isLo ? hlo : hhi)
                            + (size_t)row * HID + grpA * 512 + (kc + 1) * 64 + seg * 8);
                    }
                }
                const __nv_bfloat16* HhC = Hbase + (grp * 2 + cur) * HSZ;
                const __nv_bfloat16* HlC = Hbase + (4 + grp * 2 + cur) * HSZ;
#pragma unroll
                for (int ks = 0; ks < 4; ks++) {
                    int ko = ks * 16 + 2 * tq;
                    int r0 = wm * 16 + g, r1 = r0 + 8;
                    uint32_t ah[4], al[4];
                    ah[0] = *(const uint32_t*)&HhC[r0 * HSTR + ko];
                    ah[1] = *(const uint32_t*)&HhC[r1 * HSTR + ko];
                    ah[2] = *(const uint32_t*)&HhC[r0 * HSTR + ko + 8];
                    ah[3] = *(const uint32_t*)&HhC[r1 * HSTR + ko + 8];
                    al[0] = *(const uint32_t*)&HlC[r0 * HSTR + ko];
                    al[1] = *(const uint32_t*)&HlC[r1 * HSTR + ko];
                    al[2] = *(const uint32_t*)&HlC[r0 * HSTR + ko + 8];
                    al[3] = *(const uint32_t*)&HlC[r1 * HSTR + ko + 8];
                    int kR = grp * 512 + kc * 64 + ks * 16 + 2 * tq;
#pragma unroll
                    for (int nt = 0; nt < 4; nt++) {
                        int rr = nt * 8 + g;
                        uint32_t bh[2], bl[2];
                        bh[0] = *(const uint32_t*)&Rh[rr * RSTR + kR];
                        bh[1] = *(const uint32_t*)&Rh[rr * RSTR + kR + 8];
                        bl[0] = *(const uint32_t*)&Rl[rr * RSTR + kR];
                        bl[1] = *(const uint32_t*)&Rl[rr * RSTR + kR + 8];
                        mma16816(acc[nt], ah, bh);
                        mma16816(acc[nt], ah, bl);
                        mma16816(acc[nt], al, bh);
                    }
                }
                __syncthreads();
                if (kc < 7) {
#pragma unroll
                    for (int rep = 0; rep < 8; rep++) {
                        int arr = rep >> 1;
                        int idx = (rep & 1) * 256 + tid;
                        int row = idx >> 3, seg = idx & 7;
                        int isLo = arr >> 1, grpA = arr & 1;
                        __nv_bfloat16* dst = Hbase
                            + (isLo * 4 + grpA * 2 + (cur ^ 1)) * HSZ
                            + row * HSTR + seg * 8;
                        *(uint4*)dst = pf[rep];
                    }
                    __syncthreads();
                }
            }
        }

        // cross-group reduction (group 1 -> smem, group 0 adds)
        if (grp == 1) {
            float* r = Red + (tid & 127) * 17;
#pragma unroll
            for (int nt = 0; nt < 4; nt++)
#pragma unroll
                for (int j = 0; j < 4; j++) r[nt * 4 + j] = acc[nt][j];
        }
        __syncthreads();

        if (grp == 0) {
            const float* r = Red + tid * 17;
#pragma unroll
            for (int nt = 0; nt < 4; nt++)
#pragma unroll
                for (int j = 0; j < 4; j++) acc[nt][j] += r[nt * 4 + j];

            const float* wx_t = g_wx + (size_t)t * BATCH * GATES;
            float* h_out = out_base + (size_t)t * BATCH * HID;
            int cb = t & 1;
#pragma unroll
            for (int j = 0; j < 4; j++) {
                int brow = wm * 16 + g + ((j >> 1) * 8);
                int col  = hc0 + 2 * tq + (j & 1);
                const float* wb = wx_t + (size_t)brow * GATES;
                float vi = acc[0][j] + wb[0 * HID + col];
                float vg = acc[1][j] + wb[1 * HID + col];
                float vf = acc[2][j] + wb[2 * HID + col];
                float vo = acc[3][j] + wb[3 * HID + col];
                float ii = 1.f / (1.f + __expf(-vi));
                float gg = tanhf(vg);
                float ff = 1.f / (1.f + __expf(-vf));
                float oo = 1.f / (1.f + __expf(-vo));
                int idx = brow * HID + col;
                float cp = (t > 0) ? g_c[idx] : 0.f;   // CTA-private region
                float cn = ff * cp + ii * gg;
                g_c[idx] = cn;
                float h = oo * tanhf(cn);
                h_out[idx] = h;
                __nv_bfloat16 hi, lo;
                split_bf16(h, hi, lo);
                g_hhi[cb][idx] = hi;
                g_hlo[cb][idx] = lo;
                if (t == T_STEPS - 1) {                // fold in finalize
                    size_t base = (size_t)T_STEPS * BATCH * HID;
                    out_base[base + idx] = h;
                    out_base[base + BATCH * HID + idx] = cn;
                }
            }
        }

        // device-wide barrier: all h writes visible before anyone starts t+1
        __threadfence();
        __syncthreads();
        if (tid == 0) {
            atomicAdd((unsigned*)&g_bar, 1u);
            if (t < T_STEPS - 1) {
                unsigned target = (unsigned)NCTA * (unsigned)(t + 1);
                while (g_bar < target) { }
                __threadfence();
            }
        }
        __syncthreads();
    }

    // reset counter for the next graph replay (only after ALL arrivals)
    if (blockIdx.x == 0 && tid == 0) {
        while (g_bar < (unsigned)NCTA * (unsigned)T_STEPS) { }
        g_bar = 0;
    }
}

extern "C" void kernel_launch(void* const* d_in, const int* in_sizes, int n_in,
                              void* d_out, int out_size)
{
    const float* x    = (const float*)d_in[0];
    const float* Wk   = (const float*)d_in[1];
    const float* Rk   = (const float*)d_in[2];
    const float* bias = (const float*)d_in[3];
    float* out = (float*)d_out;

    cudaFuncSetAttribute(lstm_persistent,
                         cudaFuncAttributeMaxDynamicSharedMemorySize, SMEM_PERS);

    size_t nx = (size_t)T_STEPS * BATCH * IN_DIM;
    convert_x<<<(unsigned)((nx + 255) / 256), 256>>>(x);
    convert_W<<<dim3(GATES / 32, IN_DIM / 32), dim3(32, 8)>>>(Wk);
    convert_R<<<dim3(GATES / 32, HID / 32), dim3(32, 8)>>>(Rk);

    wx_mma<<<dim3(GATES / 128, (T_STEPS * BATCH) / 128), 256>>>(bias);

    lstm_persistent<<<NCTA, 256, SMEM_PERS>>>(out);
}

// round 8
// speedup vs baseline: 1.8816x; 1.3330x over previous
#include <cuda_runtime.h>
#include <cuda_bf16.h>
#include <math.h>
#include <stdint.h>

#define T_STEPS 512
#define BATCH   64
#define IN_DIM  1024
#define HID     1024
#define GATES   4096   // 4*HID, gate order i,g,f,o
#define NCTA    128

// ---------------- device scratch ----------------
__device__ float g_wx[(size_t)T_STEPS * BATCH * GATES];   // 512 MB
__device__ unsigned g_arrive[NCTA * 8];                   // 32B-strided flags
__device__ unsigned g_bar;                                // end-of-launch cleanup

__device__ __nv_bfloat16 g_xhi[(size_t)T_STEPS * BATCH * IN_DIM];
__device__ __nv_bfloat16 g_xlo[(size_t)T_STEPS * BATCH * IN_DIM];
__device__ __nv_bfloat16 g_Wthi[(size_t)GATES * IN_DIM];   // transposed [N][K]
__device__ __nv_bfloat16 g_Wtlo[(size_t)GATES * IN_DIM];
__device__ __nv_bfloat16 g_Rthi[(size_t)GATES * HID];      // transposed [N][K]
__device__ __nv_bfloat16 g_Rtlo[(size_t)GATES * HID];
__device__ __nv_bfloat16 g_hhi[2][BATCH * HID];            // ping-pong h bf16 hi/lo
__device__ __nv_bfloat16 g_hlo[2][BATCH * HID];

// ---------------- helpers ----------------
__device__ __forceinline__ void mma16816(float* c, const uint32_t* a, const uint32_t* b)
{
    asm volatile(
        "mma.sync.aligned.m16n8k16.row.col.f32.bf16.bf16.f32 "
        "{%0,%1,%2,%3}, {%4,%5,%6,%7}, {%8,%9}, {%0,%1,%2,%3};"
        : "+f"(c[0]), "+f"(c[1]), "+f"(c[2]), "+f"(c[3])
        : "r"(a[0]), "r"(a[1]), "r"(a[2]), "r"(a[3]), "r"(b[0]), "r"(b[1]));
}

__device__ __forceinline__ void split_bf16(float v, __nv_bfloat16& hi, __nv_bfloat16& lo)
{
    hi = __float2bfloat16_rn(v);
    lo = __float2bfloat16_rn(v - __bfloat162float(hi));
}

__device__ __forceinline__ float tanh_fast(float x)
{
    float y;
    asm("tanh.approx.f32 %0, %1;" : "=f"(y) : "f"(x));
    return y;
}
__device__ __forceinline__ float sigmoid_fast(float x)
{
    return 0.5f * tanh_fast(0.5f * x) + 0.5f;
}

__device__ __forceinline__ float2 ldcg_f2(const float* p)
{
    float2 v;
    asm volatile("ld.global.cg.v2.f32 {%0,%1}, [%2];" : "=f"(v.x), "=f"(v.y) : "l"(p));
    return v;
}

// ---------------- conversion kernels ----------------
__global__ void convert_x(const float* __restrict__ x)
{
    size_t i = (size_t)blockIdx.x * blockDim.x + threadIdx.x;
    if (i < (size_t)T_STEPS * BATCH * IN_DIM) {
        __nv_bfloat16 hi, lo;
        split_bf16(x[i], hi, lo);
        g_xhi[i] = hi;
        g_xlo[i] = lo;
    }
}

__global__ void convert_W(const float* __restrict__ src)
{
    __shared__ float tile[32][33];
    int n0 = blockIdx.x * 32, k0 = blockIdx.y * 32;
    int tx = threadIdx.x, ty = threadIdx.y;
#pragma unroll
    for (int i = 0; i < 32; i += 8)
        tile[ty + i][tx] = src[(size_t)(k0 + ty + i) * GATES + n0 + tx];
    __syncthreads();
#pragma unroll
    for (int i = 0; i < 32; i += 8) {
        float v = tile[tx][ty + i];
        size_t o = (size_t)(n0 + ty + i) * IN_DIM + k0 + tx;
        __nv_bfloat16 hi, lo;
        split_bf16(v, hi, lo);
        g_Wthi[o] = hi;
        g_Wtlo[o] = lo;
    }
}

__global__ void convert_R(const float* __restrict__ src)
{
    __shared__ float tile[32][33];
    int n0 = blockIdx.x * 32, k0 = blockIdx.y * 32;
    int tx = threadIdx.x, ty = threadIdx.y;
#pragma unroll
    for (int i = 0; i < 32; i += 8)
        tile[ty + i][tx] = src[(size_t)(k0 + ty + i) * GATES + n0 + tx];
    __syncthreads();
#pragma unroll
    for (int i = 0; i < 32; i += 8) {
        float v = tile[tx][ty + i];
        size_t o = (size_t)(n0 + ty + i) * HID + k0 + tx;
        __nv_bfloat16 hi, lo;
        split_bf16(v, hi, lo);
        g_Rthi[o] = hi;
        g_Rtlo[o] = lo;
    }
}

// ---------------- wx GEMM ----------------
#define WXS 40
__global__ __launch_bounds__(256) void wx_mma(const float* __restrict__ bias)
{
    __shared__ __align__(16) __nv_bfloat16 Ah[128 * WXS], Al[128 * WXS];
    __shared__ __align__(16) __nv_bfloat16 Bh[128 * WXS], Bl[128 * WXS];

    int tid  = threadIdx.x;
    int lane = tid & 31, w = tid >> 5;
    int g = lane >> 2, tq = lane & 3;
    size_t m0 = (size_t)blockIdx.y * 128;
    int n0 = blockIdx.x * 128;
    int wm = w & 1, wn = w >> 1;

    float acc[4][4][4];
#pragma unroll
    for (int mt = 0; mt < 4; mt++)
#pragma unroll
        for (int nt = 0; nt < 4; nt++)
#pragma unroll
            for (int r = 0; r < 4; r++) acc[mt][nt][r] = 0.f;

    for (int kc = 0; kc < 32; kc++) {
        int k0 = kc * 32;
#pragma unroll
        for (int rep = 0; rep < 2; rep++) {
            int id = tid + rep * 256;
            int row = id >> 2, seg = id & 3;
            size_t asrc = (m0 + row) * IN_DIM + k0 + seg * 8;
            size_t bsrc = (size_t)(n0 + row) * IN_DIM + k0 + seg * 8;
            *(uint4*)&Ah[row * WXS + seg * 8] = *(const uint4*)&g_xhi[asrc];
            *(uint4*)&Al[row * WXS + seg * 8] = *(const uint4*)&g_xlo[asrc];
            *(uint4*)&Bh[row * WXS + seg * 8] = *(const uint4*)&g_Wthi[bsrc];
            *(uint4*)&Bl[row * WXS + seg * 8] = *(const uint4*)&g_Wtlo[bsrc];
        }
        __syncthreads();

#pragma unroll
        for (int ks = 0; ks < 2; ks++) {
            int ko = ks * 16;
            uint32_t bh[4][2], bl[4][2];
#pragma unroll
            for (int nt = 0; nt < 4; nt++) {
                int r = wn * 32 + nt * 8 + g;
                bh[nt][0] = *(const uint32_t*)&Bh[r * WXS + ko + 2 * tq];
                bh[nt][1] = *(const uint32_t*)&Bh[r * WXS + ko + 2 * tq + 8];
                bl[nt][0] = *(const uint32_t*)&Bl[r * WXS + ko + 2 * tq];
                bl[nt][1] = *(const uint32_t*)&Bl[r * WXS + ko + 2 * tq + 8];
            }
#pragma unroll
            for (int mt = 0; mt < 4; mt++) {
                int r0 = wm * 64 + mt * 16 + g, r1 = r0 + 8;
                uint32_t ah[4], al[4];
                ah[0] = *(const uint32_t*)&Ah[r0 * WXS + ko + 2 * tq];
                ah[1] = *(const uint32_t*)&Ah[r1 * WXS + ko + 2 * tq];
                ah[2] = *(const uint32_t*)&Ah[r0 * WXS + ko + 2 * tq + 8];
                ah[3] = *(const uint32_t*)&Ah[r1 * WXS + ko + 2 * tq + 8];
                al[0] = *(const uint32_t*)&Al[r0 * WXS + ko + 2 * tq];
                al[1] = *(const uint32_t*)&Al[r1 * WXS + ko + 2 * tq];
                al[2] = *(const uint32_t*)&Al[r0 * WXS + ko + 2 * tq + 8];
                al[3] = *(const uint32_t*)&Al[r1 * WXS + ko + 2 * tq + 8];
                // pass-major: no back-to-back RAW on the same acc
#pragma unroll
                for (int nt = 0; nt < 4; nt++) mma16816(acc[mt][nt], ah, bh[nt]);
#pragma unroll
                for (int nt = 0; nt < 4; nt++) mma16816(acc[mt][nt], ah, bl[nt]);
#pragma unroll
                for (int nt = 0; nt < 4; nt++) mma16816(acc[mt][nt], al, bh[nt]);
            }
        }
        __syncthreads();
    }

#pragma unroll
    for (int mt = 0; mt < 4; mt++) {
        size_t row = m0 + wm * 64 + mt * 16 + g;
#pragma unroll
        for (int nt = 0; nt < 4; nt++) {
            int col = n0 + wn * 32 + nt * 8 + 2 * tq;
            g_wx[row * GATES + col]           = acc[mt][nt][0] + bias[col];
            g_wx[row * GATES + col + 1]       = acc[mt][nt][1] + bias[col + 1];
            g_wx[(row + 8) * GATES + col]     = acc[mt][nt][2] + bias[col];
            g_wx[(row + 8) * GATES + col + 1] = acc[mt][nt][3] + bias[col + 1];
        }
    }
}

// ---------------- persistent LSTM recurrence v2 ----------------
#define RSTR 1032                 // R smem k-stride (1024 + 8 pad)
#define HSTR 72                   // H chunk k-stride (64 + 8 pad)
#define HSZ  (64 * HSTR)
#define SMEM_PERS (2 * 32 * RSTR * 2 + 8 * HSZ * 2)   // 205824 B

// cp.async one h chunk (kc) of hi+lo, both k-halves, into buffer b
__device__ __forceinline__ void stage_chunk(uint32_t hsm,
                                            const __nv_bfloat16* hhi,
                                            const __nv_bfloat16* hlo,
                                            int kc, int b, int tid)
{
#pragma unroll
    for (int rep = 0; rep < 8; rep++) {
        int arr = rep >> 1;                       // 0..3 = (isLo, half)
        int idx = (rep & 1) * 256 + tid;
        int row = idx >> 3, seg = idx & 7;
        int isLo = arr >> 1, half = arr & 1;
        const __nv_bfloat16* src = (isLo ? hlo : hhi)
            + (size_t)row * HID + half * 512 + kc * 64 + seg * 8;
        uint32_t dst = hsm + (uint32_t)(((isLo * 4 + half * 2 + b) * HSZ
                                         + row * HSTR + seg * 8) * 2);
        asm volatile("cp.async.cg.shared.global [%0], [%1], 16;" :: "r"(dst), "l"(src));
    }
    asm volatile("cp.async.commit_group;");
}

__global__ __launch_bounds__(256) void lstm_persistent(float* __restrict__ out_base)
{
    extern __shared__ __align__(16) unsigned char smem_raw[];
    __nv_bfloat16* Rh = (__nv_bfloat16*)smem_raw;
    __nv_bfloat16* Rl = Rh + 32 * RSTR;
    __nv_bfloat16* Hbase = Rl + 32 * RSTR;       // 8 bufs [isLo*4 + half*2 + db]
    float* Red = (float*)Hbase;                   // reduction scratch (after mma done)
    uint32_t hsm = (uint32_t)__cvta_generic_to_shared(Hbase);

    const int tid  = threadIdx.x;
    const int lane = tid & 31, w = tid >> 5;
    const int g = lane >> 2, tq = lane & 3;
    const int grp = w >> 2, wm = w & 3;
    const int hc0 = blockIdx.x * 8;

    // load R slice into smem once
    for (int rep = 0; rep < 16; rep++) {
        int id = rep * 256 + tid;
        int row = id >> 7, seg = id & 127;
        size_t src = (size_t)((row >> 3) * HID + hc0 + (row & 7)) * HID + seg * 8;
        *(uint4*)&Rh[row * RSTR + seg * 8] = *(const uint4*)&g_Rthi[src];
        *(uint4*)&Rl[row * RSTR + seg * 8] = *(const uint4*)&g_Rtlo[src];
    }
    __syncthreads();

    float c_reg[4] = {0.f, 0.f, 0.f, 0.f};        // cell state lives in registers (grp 0)

    for (int t = 0; t < T_STEPS; t++) {
        // prefetch wx for this step (independent of h) — hidden under mma
        float2 wxp[2][4];
        if (grp == 0) {
            const float* wx_t = g_wx + (size_t)t * BATCH * GATES;
#pragma unroll
            for (int jj = 0; jj < 2; jj++) {
                int brow = wm * 16 + g + jj * 8;
#pragma unroll
                for (int gate = 0; gate < 4; gate++)
                    wxp[jj][gate] = ldcg_f2(wx_t + (size_t)brow * GATES
                                            + gate * HID + hc0 + 2 * tq);
            }
        }

        float acc[4][4];
#pragma unroll
        for (int nt = 0; nt < 4; nt++)
#pragma unroll
            for (int r = 0; r < 4; r++) acc[nt][r] = 0.f;

        if (t > 0) {
            const __nv_bfloat16* hhi = g_hhi[(t - 1) & 1];
            const __nv_bfloat16* hlo = g_hlo[(t - 1) & 1];

            stage_chunk(hsm, hhi, hlo, 0, 0, tid);
            stage_chunk(hsm, hhi, hlo, 1, 1, tid);

            for (int kc = 0; kc < 8; kc++) {
                int cur = kc & 1;
                if (kc < 7) asm volatile("cp.async.wait_group 1;");
                else        asm volatile("cp.async.wait_group 0;");
                __syncthreads();

                const __nv_bfloat16* HhC = Hbase + (grp * 2 + cur) * HSZ;
                const __nv_bfloat16* HlC = Hbase + (4 + grp * 2 + cur) * HSZ;
#pragma unroll
                for (int ks = 0; ks < 4; ks++) {
                    int ko = ks * 16 + 2 * tq;
                    int r0 = wm * 16 + g, r1 = r0 + 8;
                    uint32_t ah[4], al[4];
                    ah[0] = *(const uint32_t*)&HhC[r0 * HSTR + ko];
                    ah[1] = *(const uint32_t*)&HhC[r1 * HSTR + ko];
                    ah[2] = *(const uint32_t*)&HhC[r0 * HSTR + ko + 8];
                    ah[3] = *(const uint32_t*)&HhC[r1 * HSTR + ko + 8];
                    al[0] = *(const uint32_t*)&HlC[r0 * HSTR + ko];
                    al[1] = *(const uint32_t*)&HlC[r1 * HSTR + ko];
                    al[2] = *(const uint32_t*)&HlC[r0 * HSTR + ko + 8];
                    al[3] = *(const uint32_t*)&HlC[r1 * HSTR + ko + 8];
                    int kR = grp * 512 + kc * 64 + ks * 16 + 2 * tq;
                    uint32_t bh[4][2], bl[4][2];
#pragma unroll
                    for (int nt = 0; nt < 4; nt++) {
                        int rr = nt * 8 + g;
                        bh[nt][0] = *(const uint32_t*)&Rh[rr * RSTR + kR];
                        bh[nt][1] = *(const uint32_t*)&Rh[rr * RSTR + kR + 8];
                        bl[nt][0] = *(const uint32_t*)&Rl[rr * RSTR + kR];
                        bl[nt][1] = *(const uint32_t*)&Rl[rr * RSTR + kR + 8];
                    }
#pragma unroll
                    for (int nt = 0; nt < 4; nt++) mma16816(acc[nt], ah, bh[nt]);
#pragma unroll
                    for (int nt = 0; nt < 4; nt++) mma16816(acc[nt], ah, bl[nt]);
#pragma unroll
                    for (int nt = 0; nt < 4; nt++) mma16816(acc[nt], al, bh[nt]);
                }
                __syncthreads();
                if (kc + 2 < 8) stage_chunk(hsm, hhi, hlo, kc + 2, cur, tid);
            }
        }

        // cross-group reduction: grp1 -> smem, grp0 adds
        if (grp == 1) {
            float* r = Red + (tid & 127) * 17;
#pragma unroll
            for (int nt = 0; nt < 4; nt++)
#pragma unroll
                for (int j = 0; j < 4; j++) r[nt * 4 + j] = acc[nt][j];
        }
        __syncthreads();

        if (grp == 0) {
            const float* r = Red + tid * 17;
#pragma unroll
            for (int nt = 0; nt < 4; nt++)
#pragma unroll
                for (int j = 0; j < 4; j++) acc[nt][j] += r[nt * 4 + j];

            float* h_out = out_base + (size_t)t * BATCH * HID;
            int cb = t & 1;
#pragma unroll
            for (int j = 0; j < 4; j++) {
                int jj = j >> 1, cm = j & 1;
                int brow = wm * 16 + g + jj * 8;
                int col  = hc0 + 2 * tq + cm;
                float vi = acc[0][j] + (cm ? wxp[jj][0].y : wxp[jj][0].x);
                float vg = acc[1][j] + (cm ? wxp[jj][1].y : wxp[jj][1].x);
                float vf = acc[2][j] + (cm ? wxp[jj][2].y : wxp[jj][2].x);
                float vo = acc[3][j] + (cm ? wxp[jj][3].y : wxp[jj][3].x);
                float ii = sigmoid_fast(vi);
                float gg = tanh_fast(vg);
                float ff = sigmoid_fast(vf);
                float oo = sigmoid_fast(vo);
                float cn = ff * c_reg[j] + ii * gg;
                c_reg[j] = cn;
                float h = oo * tanh_fast(cn);
                int idx = brow * HID + col;
                h_out[idx] = h;
                __nv_bfloat16 hi, lo;
                split_bf16(h, hi, lo);
                g_hhi[cb][idx] = hi;
                g_hlo[cb][idx] = lo;
                if (t == T_STEPS - 1) {
                    size_t base = (size_t)T_STEPS * BATCH * HID;
                    out_base[base + idx] = h;
                    out_base[base + BATCH * HID + idx] = cn;
                }
            }
        }

        // device-wide barrier: per-CTA flag slots (no atomic contention)
        if (t < T_STEPS - 1) {
            __threadfence();
            __syncthreads();
            if (tid == 0)
                asm volatile("st.global.cg.u32 [%0], %1;"
                             :: "l"(&g_arrive[blockIdx.x * 8]), "r"(t + 1));
            unsigned target = t + 1;
            bool ok;
            do {
                unsigned v = target;
                if (tid < NCTA)
                    asm volatile("ld.global.cg.u32 %0, [%1];"
                                 : "=r"(v) : "l"(&g_arrive[tid * 8]));
                ok = (v >= target);
            } while (!__syncthreads_and(ok));
            __threadfence();
        }
    }

    // cleanup for graph replay: one contended atomic per launch, CTA0 resets flags
    if (tid == 0) {
        __threadfence();
        atomicAdd(&g_bar, 1u);
        if (blockIdx.x == 0) {
            while (atomicAdd(&g_bar, 0u) < NCTA) { }
            for (int i = 0; i < NCTA; i++) g_arrive[i * 8] = 0;
            __threadfence();
            g_bar = 0;
        }
    }
}

extern "C" void kernel_launch(void* const* d_in, const int* in_sizes, int n_in,
                              void* d_out, int out_size)
{
    const float* x    = (const float*)d_in[0];
    const float* Wk   = (const float*)d_in[1];
    const float* Rk   = (const float*)d_in[2];
    const float* bias = (const float*)d_in[3];
    float* out = (float*)d_out;

    cudaFuncSetAttribute(lstm_persistent,
                         cudaFuncAttributeMaxDynamicSharedMemorySize, SMEM_PERS);

    size_t nx = (size_t)T_STEPS * BATCH * IN_DIM;
    convert_x<<<(unsigned)((nx + 255) / 256), 256>>>(x);
    convert_W<<<dim3(GATES / 32, IN_DIM / 32), dim3(32, 8)>>>(Wk);
    convert_R<<<dim3(GATES / 32, HID / 32), dim3(32, 8)>>>(Rk);

    wx_mma<<<dim3(GATES / 128, (T_STEPS * BATCH) / 128), 256>>>(bias);

    lstm_persistent<<<NCTA, 256, SMEM_PERS>>>(out);
}

// round 9
// speedup vs baseline: 1.8865x; 1.0026x over previous
#include <cuda_runtime.h>
#include <cuda_bf16.h>
#include <math.h>
#include <stdint.h>

#define T_STEPS 512
#define BATCH   64
#define IN_DIM  1024
#define HID     1024
#define GATES   4096   // 4*HID, gate order i,g,f,o
#define NCTA    128

// ---------------- device scratch ----------------
__device__ float g_wx[(size_t)T_STEPS * BATCH * GATES];   // 512 MB
__device__ unsigned g_arrive[NCTA * 8];                   // 32B-strided flags
__device__ unsigned g_bar;                                // end-of-launch cleanup

__device__ __nv_bfloat16 g_xhi[(size_t)T_STEPS * BATCH * IN_DIM];
__device__ __nv_bfloat16 g_xlo[(size_t)T_STEPS * BATCH * IN_DIM];
__device__ __nv_bfloat16 g_Wthi[(size_t)GATES * IN_DIM];   // transposed [N][K]
__device__ __nv_bfloat16 g_Wtlo[(size_t)GATES * IN_DIM];
__device__ __nv_bfloat16 g_Rthi[(size_t)GATES * HID];      // transposed [N][K]
__device__ __nv_bfloat16 g_Rtlo[(size_t)GATES * HID];
__device__ __nv_bfloat16 g_hhi[2][BATCH * HID];            // ping-pong h bf16 hi/lo
__device__ __nv_bfloat16 g_hlo[2][BATCH * HID];

// ---------------- helpers ----------------
__device__ __forceinline__ void mma16816(float* c, const uint32_t* a, const uint32_t* b)
{
    asm volatile(
        "mma.sync.aligned.m16n8k16.row.col.f32.bf16.bf16.f32 "
        "{%0,%1,%2,%3}, {%4,%5,%6,%7}, {%8,%9}, {%0,%1,%2,%3};"
        : "+f"(c[0]), "+f"(c[1]), "+f"(c[2]), "+f"(c[3])
        : "r"(a[0]), "r"(a[1]), "r"(a[2]), "r"(a[3]), "r"(b[0]), "r"(b[1]));
}

__device__ __forceinline__ void split_bf16(float v, __nv_bfloat16& hi, __nv_bfloat16& lo)
{
    hi = __float2bfloat16_rn(v);
    lo = __float2bfloat16_rn(v - __bfloat162float(hi));
}

__device__ __forceinline__ float tanh_fast(float x)
{
    float y;
    asm("tanh.approx.f32 %0, %1;" : "=f"(y) : "f"(x));
    return y;
}
__device__ __forceinline__ float sigmoid_fast(float x)
{
    return 0.5f * tanh_fast(0.5f * x) + 0.5f;
}

__device__ __forceinline__ float2 ldcg_f2(const float* p)
{
    float2 v;
    asm volatile("ld.global.cg.v2.f32 {%0,%1}, [%2];" : "=f"(v.x), "=f"(v.y) : "l"(p));
    return v;
}

// ---------------- conversion kernels ----------------
__global__ void convert_x(const float* __restrict__ x)
{
    size_t i = (size_t)blockIdx.x * blockDim.x + threadIdx.x;
    if (i < (size_t)T_STEPS * BATCH * IN_DIM) {
        __nv_bfloat16 hi, lo;
        split_bf16(x[i], hi, lo);
        g_xhi[i] = hi;
        g_xlo[i] = lo;
    }
}

__global__ void convert_W(const float* __restrict__ src)
{
    __shared__ float tile[32][33];
    int n0 = blockIdx.x * 32, k0 = blockIdx.y * 32;
    int tx = threadIdx.x, ty = threadIdx.y;
#pragma unroll
    for (int i = 0; i < 32; i += 8)
        tile[ty + i][tx] = src[(size_t)(k0 + ty + i) * GATES + n0 + tx];
    __syncthreads();
#pragma unroll
    for (int i = 0; i < 32; i += 8) {
        float v = tile[tx][ty + i];
        size_t o = (size_t)(n0 + ty + i) * IN_DIM + k0 + tx;
        __nv_bfloat16 hi, lo;
        split_bf16(v, hi, lo);
        g_Wthi[o] = hi;
        g_Wtlo[o] = lo;
    }
}

__global__ void convert_R(const float* __restrict__ src)
{
    __shared__ float tile[32][33];
    int n0 = blockIdx.x * 32, k0 = blockIdx.y * 32;
    int tx = threadIdx.x, ty = threadIdx.y;
#pragma unroll
    for (int i = 0; i < 32; i += 8)
        tile[ty + i][tx] = src[(size_t)(k0 + ty + i) * GATES + n0 + tx];
    __syncthreads();
#pragma unroll
    for (int i = 0; i < 32; i += 8) {
        float v = tile[tx][ty + i];
        size_t o = (size_t)(n0 + ty + i) * HID + k0 + tx;
        __nv_bfloat16 hi, lo;
        split_bf16(v, hi, lo);
        g_Rthi[o] = hi;
        g_Rtlo[o] = lo;
    }
}

// ---------------- wx GEMM ----------------
#define WXS 40
__global__ __launch_bounds__(256) void wx_mma(const float* __restrict__ bias)
{
    __shared__ __align__(16) __nv_bfloat16 Ah[128 * WXS], Al[128 * WXS];
    __shared__ __align__(16) __nv_bfloat16 Bh[128 * WXS], Bl[128 * WXS];

    int tid  = threadIdx.x;
    int lane = tid & 31, w = tid >> 5;
    int g = lane >> 2, tq = lane & 3;
    size_t m0 = (size_t)blockIdx.y * 128;
    int n0 = blockIdx.x * 128;
    int wm = w & 1, wn = w >> 1;

    float acc[4][4][4];
#pragma unroll
    for (int mt = 0; mt < 4; mt++)
#pragma unroll
        for (int nt = 0; nt < 4; nt++)
#pragma unroll
            for (int r = 0; r < 4; r++) acc[mt][nt][r] = 0.f;

    for (int kc = 0; kc < 32; kc++) {
        int k0 = kc * 32;
#pragma unroll
        for (int rep = 0; rep < 2; rep++) {
            int id = tid + rep * 256;
            int row = id >> 2, seg = id & 3;
            size_t asrc = (m0 + row) * IN_DIM + k0 + seg * 8;
            size_t bsrc = (size_t)(n0 + row) * IN_DIM + k0 + seg * 8;
            *(uint4*)&Ah[row * WXS + seg * 8] = *(const uint4*)&g_xhi[asrc];
            *(uint4*)&Al[row * WXS + seg * 8] = *(const uint4*)&g_xlo[asrc];
            *(uint4*)&Bh[row * WXS + seg * 8] = *(const uint4*)&g_Wthi[bsrc];
            *(uint4*)&Bl[row * WXS + seg * 8] = *(const uint4*)&g_Wtlo[bsrc];
        }
        __syncthreads();

#pragma unroll
        for (int ks = 0; ks < 2; ks++) {
            int ko = ks * 16;
            uint32_t bh[4][2], bl[4][2];
#pragma unroll
            for (int nt = 0; nt < 4; nt++) {
                int r = wn * 32 + nt * 8 + g;
                bh[nt][0] = *(const uint32_t*)&Bh[r * WXS + ko + 2 * tq];
                bh[nt][1] = *(const uint32_t*)&Bh[r * WXS + ko + 2 * tq + 8];
                bl[nt][0] = *(const uint32_t*)&Bl[r * WXS + ko + 2 * tq];
                bl[nt][1] = *(const uint32_t*)&Bl[r * WXS + ko + 2 * tq + 8];
            }
#pragma unroll
            for (int mt = 0; mt < 4; mt++) {
                int r0 = wm * 64 + mt * 16 + g, r1 = r0 + 8;
                uint32_t ah[4], al[4];
                ah[0] = *(const uint32_t*)&Ah[r0 * WXS + ko + 2 * tq];
                ah[1] = *(const uint32_t*)&Ah[r1 * WXS + ko + 2 * tq];
                ah[2] = *(const uint32_t*)&Ah[r0 * WXS + ko + 2 * tq + 8];
                ah[3] = *(const uint32_t*)&Ah[r1 * WXS + ko + 2 * tq + 8];
                al[0] = *(const uint32_t*)&Al[r0 * WXS + ko + 2 * tq];
                al[1] = *(const uint32_t*)&Al[r1 * WXS + ko + 2 * tq];
                al[2] = *(const uint32_t*)&Al[r0 * WXS + ko + 2 * tq + 8];
                al[3] = *(const uint32_t*)&Al[r1 * WXS + ko + 2 * tq + 8];
#pragma unroll
                for (int nt = 0; nt < 4; nt++) mma16816(acc[mt][nt], ah, bh[nt]);
#pragma unroll
                for (int nt = 0; nt < 4; nt++) mma16816(acc[mt][nt], ah, bl[nt]);
#pragma unroll
                for (int nt = 0; nt < 4; nt++) mma16816(acc[mt][nt], al, bh[nt]);
            }
        }
        __syncthreads();
    }

#pragma unroll
    for (int mt = 0; mt < 4; mt++) {
        size_t row = m0 + wm * 64 + mt * 16 + g;
#pragma unroll
        for (int nt = 0; nt < 4; nt++) {
            int col = n0 + wn * 32 + nt * 8 + 2 * tq;
            g_wx[row * GATES + col]           = acc[mt][nt][0] + bias[col];
            g_wx[row * GATES + col + 1]       = acc[mt][nt][1] + bias[col + 1];
            g_wx[(row + 8) * GATES + col]     = acc[mt][nt][2] + bias[col];
            g_wx[(row + 8) * GATES + col + 1] = acc[mt][nt][3] + bias[col + 1];
        }
    }
}

// ---------------- persistent LSTM recurrence v3: warp-autonomous ----------------
// 128 CTAs, 256 thr. Warp (grp = w>>2, wm = w&3) computes k in [grp*512, +512)
// for batch rows [wm*16, +16), all 32 (gate,col) outputs. Each warp stages its
// OWN 16x64 h slices (hi+lo) via per-warp cp.async double buffering — no block
// syncs in the k-loop. One sync pair for the cross-group reduction; epilogue
// split: grp0 finalizes rows jj=0, grp1 rows jj=1.
#define RSTR 1032                                 // R smem k-stride
#define HSTR 72                                   // per-warp h k-stride
#define HBUF_B (16 * HSTR * 2)                    // 2304 B per (warp,buf,hilo)
#define H_REGION (32 * HBUF_B)                    // 73728 B
#define RED_OFF (2 * 32 * RSTR * 2 + H_REGION)
#define SMEM_PERS (RED_OFF + 2 * 128 * 9 * 4)     // +9216 B reduction

__device__ __forceinline__ void stage_warp(uint32_t hbase_sm,
                                           const __nv_bfloat16* hhi,
                                           const __nv_bfloat16* hlo,
                                           int w, int grp, int wm,
                                           int kc, int b, int lane)
{
#pragma unroll
    for (int s = 0; s < 8; s++) {
        int isLo = s >> 2;
        int id = (s & 3) * 32 + lane;             // 0..127
        int row = id >> 3, segk = id & 7;
        const __nv_bfloat16* src = (isLo ? hlo : hhi)
            + (size_t)(wm * 16 + row) * HID + grp * 512 + kc * 64 + segk * 8;
        uint32_t dst = hbase_sm
            + (uint32_t)(((w * 2 + b) * 2 + isLo) * HBUF_B + row * (HSTR * 2) + segk * 16);
        asm volatile("cp.async.cg.shared.global [%0], [%1], 16;" :: "r"(dst), "l"(src));
    }
    asm volatile("cp.async.commit_group;");
}

__global__ __launch_bounds__(256) void lstm_persistent(float* __restrict__ out_base)
{
    extern __shared__ __align__(16) unsigned char smem_raw[];
    __nv_bfloat16* Rh = (__nv_bfloat16*)smem_raw;
    __nv_bfloat16* Rl = Rh + 32 * RSTR;
    __nv_bfloat16* Hbase = Rl + 32 * RSTR;
    float* Red = (float*)(smem_raw + RED_OFF);
    uint32_t hbase_sm = (uint32_t)__cvta_generic_to_shared(Hbase);

    const int tid  = threadIdx.x;
    const int lane = tid & 31, w = tid >> 5;
    const int g = lane >> 2, tq = lane & 3;
    const int grp = w >> 2, wm = w & 3;
    const int hc0 = blockIdx.x * 8;

    // load R slice into smem once
    for (int rep = 0; rep < 16; rep++) {
        int id = rep * 256 + tid;
        int row = id >> 7, seg = id & 127;
        size_t src = (size_t)((row >> 3) * HID + hc0 + (row & 7)) * HID + seg * 8;
        *(uint4*)&Rh[row * RSTR + seg * 8] = *(const uint4*)&g_Rthi[src];
        *(uint4*)&Rl[row * RSTR + seg * 8] = *(const uint4*)&g_Rtlo[src];
    }
    __syncthreads();

    float c_reg[2] = {0.f, 0.f};                  // this group's jj-half cell state

    for (int t = 0; t < T_STEPS; t++) {
        // prefetch this group's wx half (independent of h)
        float2 wxp[4];
        {
            const float* wx_t = g_wx + (size_t)t * BATCH * GATES;
            int brow = wm * 16 + g + grp * 8;
#pragma unroll
            for (int gate = 0; gate < 4; gate++)
                wxp[gate] = ldcg_f2(wx_t + (size_t)brow * GATES + gate * HID + hc0 + 2 * tq);
        }

        float acc[4][4];
#pragma unroll
        for (int nt = 0; nt < 4; nt++)
#pragma unroll
            for (int r = 0; r < 4; r++) acc[nt][r] = 0.f;

        if (t > 0) {
            const __nv_bfloat16* hhi = g_hhi[(t - 1) & 1];
            const __nv_bfloat16* hlo = g_hlo[(t - 1) & 1];

            stage_warp(hbase_sm, hhi, hlo, w, grp, wm, 0, 0, lane);
            stage_warp(hbase_sm, hhi, hlo, w, grp, wm, 1, 1, lane);

            for (int kc = 0; kc < 8; kc++) {
                int cur = kc & 1;
                if (kc < 6) asm volatile("cp.async.wait_group 1;");
                else        asm volatile("cp.async.wait_group 0;");

                const __nv_bfloat16* HhC = (const __nv_bfloat16*)
                    ((const unsigned char*)Hbase + ((w * 2 + cur) * 2 + 0) * HBUF_B);
                const __nv_bfloat16* HlC = (const __nv_bfloat16*)
                    ((const unsigned char*)Hbase + ((w * 2 + cur) * 2 + 1) * HBUF_B);
#pragma unroll
                for (int ks = 0; ks < 4; ks++) {
                    int ko = ks * 16 + 2 * tq;
                    int r0 = g, r1 = g + 8;
                    uint32_t ah[4], al[4];
                    ah[0] = *(const uint32_t*)&HhC[r0 * HSTR + ko];
                    ah[1] = *(const uint32_t*)&HhC[r1 * HSTR + ko];
                    ah[2] = *(const uint32_t*)&HhC[r0 * HSTR + ko + 8];
                    ah[3] = *(const uint32_t*)&HhC[r1 * HSTR + ko + 8];
                    al[0] = *(const uint32_t*)&HlC[r0 * HSTR + ko];
                    al[1] = *(const uint32_t*)&HlC[r1 * HSTR + ko];
                    al[2] = *(const uint32_t*)&HlC[r0 * HSTR + ko + 8];
                    al[3] = *(const uint32_t*)&HlC[r1 * HSTR + ko + 8];
                    int kR = grp * 512 + kc * 64 + ks * 16 + 2 * tq;
                    uint32_t bh[4][2], bl[4][2];
#pragma unroll
                    for (int nt = 0; nt < 4; nt++) {
                        int rr = nt * 8 + g;
                        bh[nt][0] = *(const uint32_t*)&Rh[rr * RSTR + kR];
                        bh[nt][1] = *(const uint32_t*)&Rh[rr * RSTR + kR + 8];
                        bl[nt][0] = *(const uint32_t*)&Rl[rr * RSTR + kR];
                        bl[nt][1] = *(const uint32_t*)&Rl[rr * RSTR + kR + 8];
                    }
#pragma unroll
                    for (int nt = 0; nt < 4; nt++) mma16816(acc[nt], ah, bh[nt]);
#pragma unroll
                    for (int nt = 0; nt < 4; nt++) mma16816(acc[nt], ah, bl[nt]);
#pragma unroll
                    for (int nt = 0; nt < 4; nt++) mma16816(acc[nt], al, bh[nt]);
                }
                if (kc + 2 < 8)
                    stage_warp(hbase_sm, hhi, hlo, w, grp, wm, kc + 2, cur, lane);
            }
        }

        // cross-group exchange: each group ships the jj-half it does NOT own.
        // region 0 = grp1's j{0,1} partials; region 1 = grp0's j{2,3} partials.
        {
            float* slot = Red + ((grp ^ 1) * 128 + wm * 32 + lane) * 9;
            int jbase = (grp == 1) ? 0 : 2;
#pragma unroll
            for (int nt = 0; nt < 4; nt++) {
                slot[nt * 2 + 0] = acc[nt][jbase + 0];
                slot[nt * 2 + 1] = acc[nt][jbase + 1];
            }
        }
        __syncthreads();

        {
            const float* slot = Red + (grp * 128 + wm * 32 + lane) * 9;
            int jbase = grp * 2;                   // this group's own half
            float vv[4];
#pragma unroll
            for (int nt = 0; nt < 4; nt++)
                vv[nt] = 0.f;                      // placeholder (per-j below)

            float* h_out = out_base + (size_t)t * BATCH * HID;
            int cb = t & 1;
#pragma unroll
            for (int cm = 0; cm < 2; cm++) {
                int j = jbase + cm;
                int brow = wm * 16 + g + grp * 8;
                int col  = hc0 + 2 * tq + cm;
                float vi = acc[0][j] + slot[0 * 2 + cm] + (cm ? wxp[0].y : wxp[0].x);
                float vg = acc[1][j] + slot[1 * 2 + cm] + (cm ? wxp[1].y : wxp[1].x);
                float vf = acc[2][j] + slot[2 * 2 + cm] + (cm ? wxp[2].y : wxp[2].x);
                float vo = acc[3][j] + slot[3 * 2 + cm] + (cm ? wxp[3].y : wxp[3].x);
                float ii = sigmoid_fast(vi);
                float gg = tanh_fast(vg);
                float ff = sigmoid_fast(vf);
                float oo = sigmoid_fast(vo);
                float cn = ff * c_reg[cm] + ii * gg;
                c_reg[cm] = cn;
                float h = oo * tanh_fast(cn);
                int idx = brow * HID + col;
                h_out[idx] = h;
                __nv_bfloat16 hi, lo;
                split_bf16(h, hi, lo);
                g_hhi[cb][idx] = hi;
                g_hlo[cb][idx] = lo;
                if (t == T_STEPS - 1) {
                    size_t base = (size_t)T_STEPS * BATCH * HID;
                    out_base[base + idx] = h;
                    out_base[base + BATCH * HID + idx] = cn;
                }
            }
            (void)vv;
        }

        // device-wide barrier: per-CTA flag slots
        if (t < T_STEPS - 1) {
            __threadfence();
            __syncthreads();
            if (tid == 0)
                asm volatile("st.global.cg.u32 [%0], %1;"
                             :: "l"(&g_arrive[blockIdx.x * 8]), "r"(t + 1));
            unsigned target = t + 1;
            bool ok;
            do {
                unsigned v = target;
                if (tid < NCTA)
                    asm volatile("ld.global.cg.u32 %0, [%1];"
                                 : "=r"(v) : "l"(&g_arrive[tid * 8]));
                ok = (v >= target);
            } while (!__syncthreads_and(ok));
            __threadfence();
        }
    }

    // cleanup for graph replay
    if (tid == 0) {
        __threadfence();
        atomicAdd(&g_bar, 1u);
        if (blockIdx.x == 0) {
            while (atomicAdd(&g_bar, 0u) < NCTA) { }
            for (int i = 0; i < NCTA; i++) g_arrive[i * 8] = 0;
            __threadfence();
            g_bar = 0;
        }
    }
}

extern "C" void kernel_launch(void* const* d_in, const int* in_sizes, int n_in,
                              void* d_out, int out_size)
{
    const float* x    = (const float*)d_in[0];
    const float* Wk   = (const float*)d_in[1];
    const float* Rk   = (const float*)d_in[2];
    const float* bias = (const float*)d_in[3];
    float* out = (float*)d_out;

    cudaFuncSetAttribute(lstm_persistent,
                         cudaFuncAttributeMaxDynamicSharedMemorySize, SMEM_PERS);

    size_t nx = (size_t)T_STEPS * BATCH * IN_DIM;
    convert_x<<<(unsigned)((nx + 255) / 256), 256>>>(x);
    convert_W<<<dim3(GATES / 32, IN_DIM / 32), dim3(32, 8)>>>(Wk);
    convert_R<<<dim3(GATES / 32, HID / 32), dim3(32, 8)>>>(Rk);

    wx_mma<<<dim3(GATES / 128, (T_STEPS * BATCH) / 128), 256>>>(bias);

    lstm_persistent<<<NCTA, 256, SMEM_PERS>>>(out);
}